// round 1
// baseline (speedup 1.0000x reference)
#include <cuda_runtime.h>

#define BB 2
#define DD 1536
#define LL 2048
#define NN 16
#define TL 256          // timesteps per tile
#define JJ 8            // items per lane
#define WARPS 8         // d-channels per block (1 per warp)
#define NT (LL / TL)    // 8 tiles

__device__ __forceinline__ float ex2f(float x) {
    float r; asm("ex2.approx.f32 %0, %1;" : "=f"(r) : "f"(x)); return r;
}
__device__ __forceinline__ float lg2f(float x) {
    float r; asm("lg2.approx.f32 %0, %1;" : "=f"(r) : "f"(x)); return r;
}
__device__ __forceinline__ float rcpf(float x) {
    float r; asm("rcp.approx.f32 %0, %1;" : "=f"(r) : "f"(x)); return r;
}
__device__ __forceinline__ float expfa(float x) { return ex2f(x * 1.4426950408889634f); }

// XOR swizzle on float4-vector index within a 64-vec (256-float) row:
// makes the lane access pattern (vec = 2*lane, 2*lane+1) conflict-free.
__device__ __forceinline__ int swz(int v) { return v ^ ((v >> 3) & 7); }

__global__ __launch_bounds__(256, 2) void ssm_scan_kernel(
    const float* __restrict__ x_g, const float* __restrict__ dt_g,
    const float* __restrict__ A_g, const float* __restrict__ B_g,
    const float* __restrict__ C_g, const float* __restrict__ D_g,
    const float* __restrict__ z_g, const float* __restrict__ db_g,
    float* __restrict__ out_g)
{
    __shared__ float4 Bs[NN * 64];   // 16 KB, swizzled [n][vec]
    __shared__ float4 Cs[NN * 64];   // 16 KB

    const int b    = blockIdx.y;
    const int w    = threadIdx.x >> 5;
    const int lane = threadIdx.x & 31;
    const int d    = blockIdx.x * WARPS + w;

    const float* xp  = x_g  + (size_t)(b * DD + d) * LL;
    const float* dtp = dt_g + (size_t)(b * DD + d) * LL;
    const float* zp  = z_g  + (size_t)(b * DD + d) * LL;
    float*       op  = out_g + (size_t)(b * DD + d) * LL;

    const float4* Bg4 = (const float4*)(B_g + (size_t)b * NN * LL);
    const float4* Cg4 = (const float4*)(C_g + (size_t)b * NN * LL);

    // Per-warp-uniform channel constants
    float A2[NN];
#pragma unroll
    for (int n = 0; n < NN; n++) A2[n] = A_g[d * NN + n] * 1.4426950408889634f;
    const float db = db_g[d];
    const float Dd = D_g[d];

    // Carried scan state per n (warp-uniform value held in every lane)
    float hc[NN];
#pragma unroll
    for (int n = 0; n < NN; n++) hc[n] = 0.0f;

    const int sv0 = swz(2 * lane);
    const int sv1 = swz(2 * lane + 1);

    for (int t = 0; t < NT; t++) {
        const int l0 = t * TL;

        __syncthreads();   // previous tile's smem reads complete
        // Stage B,C tile: 2*16*64 float4 = 2048 vecs, 256 threads * 4 each per array
#pragma unroll
        for (int k = 0; k < 4; k++) {
            int v  = threadIdx.x + k * 256;      // 0..1023
            int n  = v >> 6;
            int vc = v & 63;
            Bs[n * 64 + swz(vc)] = Bg4[n * (LL / 4) + (l0 / 4) + vc];
            Cs[n * 64 + swz(vc)] = Cg4[n * (LL / 4) + (l0 / 4) + vc];
        }
        __syncthreads();

        // Per-lane loads for its 8 contiguous timesteps
        const int base = l0 + lane * JJ;
        float4 t0 = *(const float4*)(dtp + base);
        float4 t1 = *(const float4*)(dtp + base + 4);
        float4 x0 = *(const float4*)(xp + base);
        float4 x1 = *(const float4*)(xp + base + 4);

        float xv[JJ] = {x0.x, x0.y, x0.z, x0.w, x1.x, x1.y, x1.z, x1.w};
        float dv[JJ] = {t0.x, t0.y, t0.z, t0.w, t1.x, t1.y, t1.z, t1.w};
        float dpv[JJ], du[JJ], y[JJ];
#pragma unroll
        for (int j = 0; j < JJ; j++) {
            float v  = dv[j] + db;
            float sp = lg2f(1.0f + expfa(v)) * 0.6931471805599453f;  // softplus
            dpv[j] = (v > 15.0f) ? v : sp;
            du[j]  = dpv[j] * xv[j];
            y[j]   = 0.0f;
        }

#pragma unroll
        for (int n = 0; n < NN; n++) {
            const float a2  = A2[n];
            const float hcn = hc[n];
            float4 bv0 = Bs[n * 64 + sv0];
            float4 bv1 = Bs[n * 64 + sv1];
            float Bv[JJ] = {bv0.x, bv0.y, bv0.z, bv0.w, bv1.x, bv1.y, bv1.z, bv1.w};

            // Phase A: lane-local inclusive compose over its 8 items
            float ac[JJ], bc[JJ];
            float a   = ex2f(dpv[0] * a2);
            float acr = a;
            float bcr = du[0] * Bv[0];
            ac[0] = acr; bc[0] = bcr;
#pragma unroll
            for (int j = 1; j < JJ; j++) {
                a   = ex2f(dpv[j] * a2);
                bcr = fmaf(a, bcr, du[j] * Bv[j]);
                acr = acr * a;
                ac[j] = acr; bc[j] = bcr;
            }

            // Phase B: warp inclusive scan of lane aggregates
#pragma unroll
            for (int off = 1; off < 32; off <<= 1) {
                float ap = __shfl_up_sync(0xffffffffu, acr, off);
                float bp = __shfl_up_sync(0xffffffffu, bcr, off);
                if (lane >= off) { bcr = fmaf(acr, bp, bcr); acr *= ap; }
            }
            float aE = __shfl_up_sync(0xffffffffu, acr, 1);
            float bE = __shfl_up_sync(0xffffffffu, bcr, 1);
            float aL = __shfl_sync(0xffffffffu, acr, 31);
            float bL = __shfl_sync(0xffffffffu, bcr, 31);
            float h_in = (lane == 0) ? hcn : fmaf(aE, hcn, bE);
            hc[n] = fmaf(aL, hcn, bL);   // carry to next tile (warp-uniform)

            // Phase C: materialize h per item, accumulate y
            float4 cv0 = Cs[n * 64 + sv0];
            float4 cv1 = Cs[n * 64 + sv1];
            float Cv[JJ] = {cv0.x, cv0.y, cv0.z, cv0.w, cv1.x, cv1.y, cv1.z, cv1.w};
#pragma unroll
            for (int j = 0; j < JJ; j++) {
                float h = fmaf(ac[j], h_in, bc[j]);
                y[j] = fmaf(h, Cv[j], y[j]);
            }
        }

        // Epilogue: D-skip + SiLU gate, write out
        float4 z0 = *(const float4*)(zp + base);
        float4 z1 = *(const float4*)(zp + base + 4);
        float zv[JJ] = {z0.x, z0.y, z0.z, z0.w, z1.x, z1.y, z1.z, z1.w};
        float ov[JJ];
#pragma unroll
        for (int j = 0; j < JJ; j++) {
            float sil = zv[j] * rcpf(1.0f + expfa(-zv[j]));
            ov[j] = fmaf(xv[j], Dd, y[j]) * sil;
        }
        float4 o0 = {ov[0], ov[1], ov[2], ov[3]};
        float4 o1 = {ov[4], ov[5], ov[6], ov[7]};
        *(float4*)(op + base)     = o0;
        *(float4*)(op + base + 4) = o1;
    }
}

extern "C" void kernel_launch(void* const* d_in, const int* in_sizes, int n_in,
                              void* d_out, int out_size) {
    const float* x   = (const float*)d_in[0];
    const float* dt  = (const float*)d_in[1];
    const float* A   = (const float*)d_in[2];
    const float* B   = (const float*)d_in[3];
    const float* C   = (const float*)d_in[4];
    const float* D   = (const float*)d_in[5];
    const float* z   = (const float*)d_in[6];
    const float* dbb = (const float*)d_in[7];
    float* out = (float*)d_out;

    dim3 grid(DD / WARPS, BB);   // (192, 2)
    ssm_scan_kernel<<<grid, 256>>>(x, dt, A, B, C, D, z, dbb, out);
}

// round 2
// speedup vs baseline: 1.0684x; 1.0684x over previous
#include <cuda_runtime.h>

#define BB 2
#define DD 1536
#define LL 2048
#define NN 16
#define TL 256          // timesteps per tile
#define JJ 8            // items per lane
#define WARPS 4         // d-channels per block (1 per warp), 128 threads
#define NT (LL / TL)    // 8 tiles

__device__ __forceinline__ float ex2f(float x) {
    float r; asm("ex2.approx.f32 %0, %1;" : "=f"(r) : "f"(x)); return r;
}
__device__ __forceinline__ float lg2f(float x) {
    float r; asm("lg2.approx.f32 %0, %1;" : "=f"(r) : "f"(x)); return r;
}
__device__ __forceinline__ float rcpf(float x) {
    float r; asm("rcp.approx.f32 %0, %1;" : "=f"(r) : "f"(x)); return r;
}
__device__ __forceinline__ float expfa(float x) { return ex2f(x * 1.4426950408889634f); }

// XOR swizzle on float4-vector index within a 64-vec (256-float) row:
// makes the lane access pattern (vec = 2*lane, 2*lane+1) conflict-free.
__device__ __forceinline__ int swz(int v) { return v ^ ((v >> 3) & 7); }

__global__ __launch_bounds__(128, 6) void ssm_scan_kernel(
    const float* __restrict__ x_g, const float* __restrict__ dt_g,
    const float* __restrict__ A_g, const float* __restrict__ B_g,
    const float* __restrict__ C_g, const float* __restrict__ D_g,
    const float* __restrict__ z_g, const float* __restrict__ db_g,
    float* __restrict__ out_g)
{
    __shared__ float4 Bs[NN * 64];      // 16 KB, swizzled [n][vec]
    __shared__ float4 Cs[NN * 64];      // 16 KB
    __shared__ float  As_sm[WARPS][NN]; // A * log2e, per warp
    __shared__ float  hcs[WARPS][NN];   // carried scan state, per warp

    const int b    = blockIdx.y;
    const int w    = threadIdx.x >> 5;
    const int lane = threadIdx.x & 31;
    const int d    = blockIdx.x * WARPS + w;

    const float* xp  = x_g  + (size_t)(b * DD + d) * LL;
    const float* dtp = dt_g + (size_t)(b * DD + d) * LL;
    const float* zp  = z_g  + (size_t)(b * DD + d) * LL;
    float*       op  = out_g + (size_t)(b * DD + d) * LL;

    const float4* Bg4 = (const float4*)(B_g + (size_t)b * NN * LL);
    const float4* Cg4 = (const float4*)(C_g + (size_t)b * NN * LL);

    if (lane < NN) {
        As_sm[w][lane] = A_g[d * NN + lane] * 1.4426950408889634f;
        hcs[w][lane]   = 0.0f;
    }
    const float db = db_g[d];
    const float Dd = D_g[d];

    const int sv0 = swz(2 * lane);
    const int sv1 = swz(2 * lane + 1);

    for (int t = 0; t < NT; t++) {
        const int l0 = t * TL;

        __syncthreads();   // previous tile's smem reads / state writes complete
        // Stage B,C tile: 2*16*64 float4 = 2048 vecs, 128 threads * 8 each per array
#pragma unroll
        for (int k = 0; k < 8; k++) {
            int v  = threadIdx.x + k * 128;      // 0..1023
            int n  = v >> 6;
            int vc = v & 63;
            Bs[n * 64 + swz(vc)] = Bg4[n * (LL / 4) + (l0 / 4) + vc];
            Cs[n * 64 + swz(vc)] = Cg4[n * (LL / 4) + (l0 / 4) + vc];
        }
        __syncthreads();

        // Per-lane loads for its 8 contiguous timesteps
        const int base = l0 + lane * JJ;
        float4 t0 = *(const float4*)(dtp + base);
        float4 t1 = *(const float4*)(dtp + base + 4);
        float4 x0 = *(const float4*)(xp + base);
        float4 x1 = *(const float4*)(xp + base + 4);

        float dpv[JJ], du[JJ], y[JJ];
        {
            float xv[JJ] = {x0.x, x0.y, x0.z, x0.w, x1.x, x1.y, x1.z, x1.w};
            float dv[JJ] = {t0.x, t0.y, t0.z, t0.w, t1.x, t1.y, t1.z, t1.w};
#pragma unroll
            for (int j = 0; j < JJ; j++) {
                float v  = dv[j] + db;
                float sp = lg2f(1.0f + expfa(v)) * 0.6931471805599453f;  // softplus
                dpv[j] = (v > 15.0f) ? v : sp;
                du[j]  = dpv[j] * xv[j];
                y[j]   = 0.0f;
            }
        }

#pragma unroll
        for (int n = 0; n < NN; n++) {
            const float a2  = As_sm[w][n];
            const float hcn = hcs[w][n];
            float4 bv0 = Bs[n * 64 + sv0];
            float4 bv1 = Bs[n * 64 + sv1];
            float Bv[JJ] = {bv0.x, bv0.y, bv0.z, bv0.w, bv1.x, bv1.y, bv1.z, bv1.w};

            // Phase A: lane-local inclusive compose over its 8 items.
            // Carry is folded into lane 0's seed, so the scanned b IS the h value.
            float ac[JJ], bc[JJ];
            const float seed = (lane == 0) ? hcn : 0.0f;
            float a   = ex2f(dpv[0] * a2);
            float acr = a;
            float bcr = fmaf(a, seed, du[0] * Bv[0]);
            ac[0] = acr; bc[0] = bcr;
#pragma unroll
            for (int j = 1; j < JJ; j++) {
                a   = ex2f(dpv[j] * a2);
                bcr = fmaf(a, bcr, du[j] * Bv[j]);
                acr = acr * a;
                ac[j] = acr; bc[j] = bcr;
            }

            // Phase B: warp inclusive scan of lane aggregates
#pragma unroll
            for (int off = 1; off < 32; off <<= 1) {
                float ap = __shfl_up_sync(0xffffffffu, acr, off);
                float bp = __shfl_up_sync(0xffffffffu, bcr, off);
                if (lane >= off) { bcr = fmaf(acr, bp, bcr); acr *= ap; }
            }
            // h entering this lane = inclusive h of previous lane (carry embedded)
            float bE   = __shfl_up_sync(0xffffffffu, bcr, 1);
            float h_in = (lane == 0) ? 0.0f : bE;
            float hnew = __shfl_sync(0xffffffffu, bcr, 31);
            if (lane == 0) hcs[w][n] = hnew;   // carry to next tile

            // Phase C: materialize h per item, accumulate y
            float4 cv0 = Cs[n * 64 + sv0];
            float4 cv1 = Cs[n * 64 + sv1];
            float Cv[JJ] = {cv0.x, cv0.y, cv0.z, cv0.w, cv1.x, cv1.y, cv1.z, cv1.w};
#pragma unroll
            for (int j = 0; j < JJ; j++) {
                float h = fmaf(ac[j], h_in, bc[j]);
                y[j] = fmaf(h, Cv[j], y[j]);
            }
        }

        // Epilogue: D-skip + SiLU gate, write out (x reloaded — L1 hit)
        float4 z0 = *(const float4*)(zp + base);
        float4 z1 = *(const float4*)(zp + base + 4);
        float4 xr0 = *(const float4*)(xp + base);
        float4 xr1 = *(const float4*)(xp + base + 4);
        float zv[JJ] = {z0.x, z0.y, z0.z, z0.w, z1.x, z1.y, z1.z, z1.w};
        float xw[JJ] = {xr0.x, xr0.y, xr0.z, xr0.w, xr1.x, xr1.y, xr1.z, xr1.w};
        float ov[JJ];
#pragma unroll
        for (int j = 0; j < JJ; j++) {
            float sil = zv[j] * rcpf(1.0f + expfa(-zv[j]));
            ov[j] = fmaf(xw[j], Dd, y[j]) * sil;
        }
        float4 o0 = {ov[0], ov[1], ov[2], ov[3]};
        float4 o1 = {ov[4], ov[5], ov[6], ov[7]};
        *(float4*)(op + base)     = o0;
        *(float4*)(op + base + 4) = o1;
    }
}

extern "C" void kernel_launch(void* const* d_in, const int* in_sizes, int n_in,
                              void* d_out, int out_size) {
    const float* x   = (const float*)d_in[0];
    const float* dt  = (const float*)d_in[1];
    const float* A   = (const float*)d_in[2];
    const float* B   = (const float*)d_in[3];
    const float* C   = (const float*)d_in[4];
    const float* D   = (const float*)d_in[5];
    const float* z   = (const float*)d_in[6];
    const float* dbb = (const float*)d_in[7];
    float* out = (float*)d_out;

    dim3 grid(DD / WARPS, BB);   // (384, 2) = 768 blocks of 128 threads
    ssm_scan_kernel<<<grid, 128>>>(x, dt, A, B, C, D, z, dbb, out);
}